// round 1
// baseline (speedup 1.0000x reference)
#include <cuda_runtime.h>

#define NN 100000
#define NE 1600000

// ---- device scratch (no allocs allowed) ----
__device__ float g_h1 [NN * 64];
__device__ float g_as1[NN * 8];
__device__ float g_ad1[NN * 8];
__device__ float g_den1[NN * 8];
__device__ float g_acc1[NN * 64];
__device__ float g_h2 [NN * 2];
__device__ float g_as2[NN];
__device__ float g_ad2[NN];
__device__ float g_den2[NN];
__device__ float g_acc2[NN * 2];
__device__ int   g_is64;

// Detect whether edge_index is int64 or int32 (JAX x64 flag dependent).
// int64 node ids < 2^31 -> every high 32-bit word is zero.
__global__ void k_detect(const unsigned* __restrict__ ei) {
    g_is64 = ((ei[1] | ei[3] | ei[5] | ei[7]) == 0u) ? 1 : 0;
}

__device__ __forceinline__ void load_edge(const void* ei, long long e, int is64,
                                          int& src, int& dst) {
    if (is64) {
        const long long* p = (const long long*)ei;
        src = (int)p[e];
        dst = (int)p[NE + e];
    } else {
        const int* p = (const int*)ei;
        src = p[e];
        dst = p[NE + e];
    }
}

// ---- layer 1: node prep (h1 = x@W1, alpha_src/dst, zero accumulators) ----
__global__ void k_prep1(const float* __restrict__ x, const float* __restrict__ W1,
                        const float* __restrict__ aw, const float* __restrict__ bw) {
    __shared__ float sW[320], sA[64], sB[64];
    int t = threadIdx.x;
    for (int i = t; i < 320; i += blockDim.x) sW[i] = W1[i];
    for (int i = t; i < 64; i += blockDim.x) { sA[i] = aw[i]; sB[i] = bw[i]; }
    __syncthreads();
    int n = blockIdx.x * blockDim.x + t;
    if (n >= NN) return;

    float xv[5];
#pragma unroll
    for (int k = 0; k < 5; k++) xv[k] = x[n * 5 + k];

    float h[64];
#pragma unroll
    for (int j = 0; j < 64; j++) {
        float s = xv[0] * sW[j];
        s = fmaf(xv[1], sW[64 + j], s);
        s = fmaf(xv[2], sW[128 + j], s);
        s = fmaf(xv[3], sW[192 + j], s);
        s = fmaf(xv[4], sW[256 + j], s);
        h[j] = s;
    }

    float4* hp = (float4*)(g_h1 + (size_t)n * 64);
    float4* ap = (float4*)(g_acc1 + (size_t)n * 64);
    float4 z = make_float4(0.f, 0.f, 0.f, 0.f);
#pragma unroll
    for (int q = 0; q < 16; q++) {
        hp[q] = make_float4(h[4 * q], h[4 * q + 1], h[4 * q + 2], h[4 * q + 3]);
        ap[q] = z;
    }
#pragma unroll
    for (int hh = 0; hh < 8; hh++) {
        float sa = 0.f, sb = 0.f;
#pragma unroll
        for (int c = 0; c < 8; c++) {
            sa = fmaf(h[hh * 8 + c], sA[hh * 8 + c], sa);
            sb = fmaf(h[hh * 8 + c], sB[hh * 8 + c], sb);
        }
        g_as1[n * 8 + hh] = sa;
        g_ad1[n * 8 + hh] = sb;
        g_den1[n * 8 + hh] = 0.f;
    }
}

// ---- layer 1: edge pass (8 threads per edge, one head each) ----
__global__ void k_edge1(const void* __restrict__ ei) {
    long long tid = (long long)blockIdx.x * blockDim.x + threadIdx.x;
    long long e = tid >> 3;
    int hh = (int)(tid & 7);
    if (e >= NE) return;
    int is64 = g_is64;
    int src, dst;
    load_edge(ei, e, is64, src, dst);

    float v = g_as1[src * 8 + hh] + g_ad1[dst * 8 + hh];
    v = v > 0.f ? v : 0.2f * v;
    float w = __expf(v);

    asm volatile("red.global.add.f32 [%0], %1;" ::"l"(g_den1 + dst * 8 + hh), "f"(w)
                 : "memory");

    const float4* hs = (const float4*)(g_h1 + (size_t)src * 64 + hh * 8);
    float4 a = hs[0], b = hs[1];
    float4* dp = (float4*)(g_acc1 + (size_t)dst * 64 + hh * 8);
    asm volatile("red.global.add.v4.f32 [%0], {%1,%2,%3,%4};" ::"l"(dp),
                 "f"(w * a.x), "f"(w * a.y), "f"(w * a.z), "f"(w * a.w)
                 : "memory");
    asm volatile("red.global.add.v4.f32 [%0], {%1,%2,%3,%4};" ::"l"(dp + 1),
                 "f"(w * b.x), "f"(w * b.y), "f"(w * b.z), "f"(w * b.w)
                 : "memory");
}

// ---- finalize layer 1 (self-loop + softmax norm + bias + elu) fused with
// ---- layer-2 node prep (h2 = h1out@W2, alpha2, zero accumulators) ----
__global__ void k_fin1(const float* __restrict__ b1, const float* __restrict__ W2,
                       const float* __restrict__ a2, const float* __restrict__ d2) {
    __shared__ float sW2[128], sb1[64], sa2[2], sd2[2];
    int t = threadIdx.x;
    for (int i = t; i < 128; i += blockDim.x) sW2[i] = W2[i];
    for (int i = t; i < 64; i += blockDim.x) sb1[i] = b1[i];
    if (t < 2) { sa2[t] = a2[t]; sd2[t] = d2[t]; }
    __syncthreads();
    int n = blockIdx.x * blockDim.x + t;
    if (n >= NN) return;

    float h20 = 0.f, h21 = 0.f;
#pragma unroll
    for (int hh = 0; hh < 8; hh++) {
        float av = g_as1[n * 8 + hh] + g_ad1[n * 8 + hh];
        av = av > 0.f ? av : 0.2f * av;
        float w = __expf(av);
        float inv = 1.f / (g_den1[n * 8 + hh] + w);
#pragma unroll
        for (int c = 0; c < 8; c++) {
            int j = hh * 8 + c;
            float hv = g_h1[(size_t)n * 64 + j];
            float o = (g_acc1[(size_t)n * 64 + j] + w * hv) * inv + sb1[j];
            o = o > 0.f ? o : expm1f(o);  // elu
            h20 = fmaf(o, sW2[j * 2], h20);
            h21 = fmaf(o, sW2[j * 2 + 1], h21);
        }
    }
    g_h2[n * 2] = h20;
    g_h2[n * 2 + 1] = h21;
    g_as2[n] = h20 * sa2[0] + h21 * sa2[1];
    g_ad2[n] = h20 * sd2[0] + h21 * sd2[1];
    g_den2[n] = 0.f;
    g_acc2[n * 2] = 0.f;
    g_acc2[n * 2 + 1] = 0.f;
}

// ---- layer 2: edge pass (1 thread per edge) ----
__global__ void k_edge2(const void* __restrict__ ei) {
    long long e = (long long)blockIdx.x * blockDim.x + threadIdx.x;
    if (e >= NE) return;
    int is64 = g_is64;
    int src, dst;
    load_edge(ei, e, is64, src, dst);

    float v = g_as2[src] + g_ad2[dst];
    v = v > 0.f ? v : 0.2f * v;
    float w = __expf(v);
    asm volatile("red.global.add.f32 [%0], %1;" ::"l"(g_den2 + dst), "f"(w)
                 : "memory");
    float2 h = *(const float2*)(g_h2 + (size_t)src * 2);
    asm volatile("red.global.add.v2.f32 [%0], {%1,%2};" ::"l"(
                     (float2*)(g_acc2 + (size_t)dst * 2)),
                 "f"(w * h.x), "f"(w * h.y)
                 : "memory");
}

// ---- finalize layer 2 + log_softmax ----
__global__ void k_fin2(float* __restrict__ out, const float* __restrict__ b2) {
    int n = blockIdx.x * blockDim.x + threadIdx.x;
    if (n >= NN) return;
    float v = g_as2[n] + g_ad2[n];
    v = v > 0.f ? v : 0.2f * v;
    float w = __expf(v);
    float inv = 1.f / (g_den2[n] + w);
    float o0 = (g_acc2[n * 2] + w * g_h2[n * 2]) * inv + b2[0];
    float o1 = (g_acc2[n * 2 + 1] + w * g_h2[n * 2 + 1]) * inv + b2[1];
    float m = fmaxf(o0, o1);
    float lse = m + log1pf(__expf(fminf(o0, o1) - m));
    out[n * 2] = o0 - lse;
    out[n * 2 + 1] = o1 - lse;
}

extern "C" void kernel_launch(void* const* d_in, const int* in_sizes, int n_in,
                              void* d_out, int out_size) {
    const float* x   = (const float*)d_in[0];
    const void*  ei  = d_in[1];
    const float* W1  = (const float*)d_in[2];
    const float* as1 = (const float*)d_in[3];
    const float* ad1 = (const float*)d_in[4];
    const float* b1  = (const float*)d_in[5];
    const float* W2  = (const float*)d_in[6];
    const float* as2 = (const float*)d_in[7];
    const float* ad2 = (const float*)d_in[8];
    const float* b2  = (const float*)d_in[9];
    float* out = (float*)d_out;

    k_detect<<<1, 1>>>((const unsigned*)ei);
    k_prep1<<<(NN + 255) / 256, 256>>>(x, W1, as1, ad1);
    {
        long long total = (long long)NE * 8;
        k_edge1<<<(unsigned)((total + 255) / 256), 256>>>(ei);
    }
    k_fin1<<<(NN + 255) / 256, 256>>>(b1, W2, as2, ad2);
    k_edge2<<<(NE + 255) / 256, 256>>>(ei);
    k_fin2<<<(NN + 255) / 256, 256>>>(out, b2);
}

// round 2
// speedup vs baseline: 1.3098x; 1.3098x over previous
#include <cuda_runtime.h>

#define NN 100000
#define NE 1600000

// ---- device scratch ----
__device__ float g_sx  [NN * 8];   // {x0..x4, pad,pad,pad} per node
__device__ float g_as1 [NN * 8];   // per-head alpha_src
__device__ float g_ad1 [NN * 8];   // per-head alpha_dst
__device__ float g_acc1[NN * 64];  // [n][head][8]: {w*x0..w*x3, w*x4, sum_w, pad, pad}
__device__ float4 g_src2[NN];      // {h2_0, h2_1, alpha_src2, 0}
__device__ float  g_ad2 [NN];
__device__ float4 g_acc2[NN];      // {sum w*h0, sum w*h1, sum w, 0}
__device__ int    g_is64;

__global__ void k_detect(const unsigned* __restrict__ ei) {
    g_is64 = ((ei[1] | ei[3] | ei[5] | ei[7]) == 0u) ? 1 : 0;
}

__device__ __forceinline__ void load_edge(const void* ei, int e, int is64,
                                          int& src, int& dst) {
    if (is64) {
        const long long* p = (const long long*)ei;
        src = (int)__ldg(p + e);
        dst = (int)__ldg(p + NE + e);
    } else {
        const int* p = (const int*)ei;
        src = __ldg(p + e);
        dst = __ldg(p + NE + e);
    }
}

// ---- layer 1 node prep: alpha_src/dst from h = x@W1 (h stays in regs), pad x,
// ---- zero accumulators ----
__global__ void k_prep1(const float* __restrict__ x, const float* __restrict__ W1,
                        const float* __restrict__ aw, const float* __restrict__ bw) {
    __shared__ float sW[320], sA[64], sB[64];
    int t = threadIdx.x;
    for (int i = t; i < 320; i += blockDim.x) sW[i] = W1[i];
    for (int i = t; i < 64; i += blockDim.x) { sA[i] = aw[i]; sB[i] = bw[i]; }
    __syncthreads();
    int n = blockIdx.x * blockDim.x + t;
    if (n >= NN) return;

    float xv[5];
#pragma unroll
    for (int k = 0; k < 5; k++) xv[k] = x[n * 5 + k];

    float4* sx = (float4*)(g_sx + n * 8);
    sx[0] = make_float4(xv[0], xv[1], xv[2], xv[3]);
    sx[1] = make_float4(xv[4], 0.f, 0.f, 0.f);

    float as[8], ad[8];
#pragma unroll
    for (int hh = 0; hh < 8; hh++) {
        float sa = 0.f, sb = 0.f;
#pragma unroll
        for (int c = 0; c < 8; c++) {
            int j = hh * 8 + c;
            float h = xv[0] * sW[j];
            h = fmaf(xv[1], sW[64 + j], h);
            h = fmaf(xv[2], sW[128 + j], h);
            h = fmaf(xv[3], sW[192 + j], h);
            h = fmaf(xv[4], sW[256 + j], h);
            sa = fmaf(h, sA[j], sa);
            sb = fmaf(h, sB[j], sb);
        }
        as[hh] = sa;
        ad[hh] = sb;
    }
    float4* ap = (float4*)(g_as1 + n * 8);
    ap[0] = make_float4(as[0], as[1], as[2], as[3]);
    ap[1] = make_float4(as[4], as[5], as[6], as[7]);
    float4* dp = (float4*)(g_ad1 + n * 8);
    dp[0] = make_float4(ad[0], ad[1], ad[2], ad[3]);
    dp[1] = make_float4(ad[4], ad[5], ad[6], ad[7]);

    float4 z = make_float4(0.f, 0.f, 0.f, 0.f);
    float4* cp = (float4*)(g_acc1 + (size_t)n * 64);
#pragma unroll
    for (int q = 0; q < 16; q++) cp[q] = z;
}

// ---- layer 1 edge pass: one thread per edge, accumulate w*x (5) + w per head
__global__ void k_edge1(const void* __restrict__ ei) {
    int e = blockIdx.x * blockDim.x + threadIdx.x;
    if (e >= NE) return;
    int is64 = g_is64;
    int src, dst;
    load_edge(ei, e, is64, src, dst);

    float4 x03 = *(const float4*)(g_sx + src * 8);
    float x4 = g_sx[src * 8 + 4];
    float4 a0 = *(const float4*)(g_as1 + src * 8);
    float4 a1 = *(const float4*)(g_as1 + src * 8 + 4);
    float4 d0 = *(const float4*)(g_ad1 + dst * 8);
    float4 d1 = *(const float4*)(g_ad1 + dst * 8 + 4);
    float av[8] = {a0.x, a0.y, a0.z, a0.w, a1.x, a1.y, a1.z, a1.w};
    float dv[8] = {d0.x, d0.y, d0.z, d0.w, d1.x, d1.y, d1.z, d1.w};

    float* accb = g_acc1 + (size_t)dst * 64;
#pragma unroll
    for (int hh = 0; hh < 8; hh++) {
        float v = av[hh] + dv[hh];
        v = v > 0.f ? v : 0.2f * v;
        float w = __expf(v);
        asm volatile("red.global.add.v4.f32 [%0], {%1,%2,%3,%4};" ::"l"(
                         accb + hh * 8),
                     "f"(w * x03.x), "f"(w * x03.y), "f"(w * x03.z), "f"(w * x03.w)
                     : "memory");
        asm volatile("red.global.add.v2.f32 [%0], {%1,%2};" ::"l"(accb + hh * 8 + 4),
                     "f"(w * x4), "f"(w)
                     : "memory");
    }
}

// ---- finalize layer 1 + elu + bias + layer-2 projection, 8 threads/node ----
__global__ void k_fin1(const float* __restrict__ W1, const float* __restrict__ b1,
                       const float* __restrict__ W2, const float* __restrict__ a2,
                       const float* __restrict__ d2) {
    __shared__ float sW1[320], sb1[64], sW2[128], sa2[2], sd2[2];
    int t = threadIdx.x;
    for (int i = t; i < 320; i += blockDim.x) sW1[i] = W1[i];
    for (int i = t; i < 128; i += blockDim.x) sW2[i] = W2[i];
    for (int i = t; i < 64; i += blockDim.x) sb1[i] = b1[i];
    if (t < 2) { sa2[t] = a2[t]; sd2[t] = d2[t]; }
    __syncthreads();

    int n = blockIdx.x * 32 + (t >> 3);
    int hh = t & 7;
    if (n >= NN) return;

    float4 A = *(const float4*)(g_acc1 + (size_t)n * 64 + hh * 8);
    float4 B = *(const float4*)(g_acc1 + (size_t)n * 64 + hh * 8 + 4);

    float ws = g_as1[n * 8 + hh] + g_ad1[n * 8 + hh];
    ws = ws > 0.f ? ws : 0.2f * ws;
    ws = __expf(ws);

    float x0 = g_sx[n * 8 + 0], x1 = g_sx[n * 8 + 1], x2 = g_sx[n * 8 + 2];
    float x3 = g_sx[n * 8 + 3], x4 = g_sx[n * 8 + 4];

    float inv = 1.f / (B.y + ws);
    float xa0 = (A.x + ws * x0) * inv;
    float xa1 = (A.y + ws * x1) * inv;
    float xa2 = (A.z + ws * x2) * inv;
    float xa3 = (A.w + ws * x3) * inv;
    float xa4 = (B.x + ws * x4) * inv;

    float h20 = 0.f, h21 = 0.f;
#pragma unroll
    for (int j = 0; j < 8; j++) {
        int jj = hh * 8 + j;
        float o = xa0 * sW1[jj];
        o = fmaf(xa1, sW1[64 + jj], o);
        o = fmaf(xa2, sW1[128 + jj], o);
        o = fmaf(xa3, sW1[192 + jj], o);
        o = fmaf(xa4, sW1[256 + jj], o);
        o += sb1[jj];
        o = o > 0.f ? o : __expf(o) - 1.f;  // elu
        h20 = fmaf(o, sW2[jj * 2], h20);
        h21 = fmaf(o, sW2[jj * 2 + 1], h21);
    }
#pragma unroll
    for (int m = 1; m < 8; m <<= 1) {
        h20 += __shfl_xor_sync(0xffffffffu, h20, m);
        h21 += __shfl_xor_sync(0xffffffffu, h21, m);
    }
    if (hh == 0) {
        float as2 = h20 * sa2[0] + h21 * sa2[1];
        float ad2 = h20 * sd2[0] + h21 * sd2[1];
        g_src2[n] = make_float4(h20, h21, as2, 0.f);
        g_ad2[n] = ad2;
        g_acc2[n] = make_float4(0.f, 0.f, 0.f, 0.f);
    }
}

// ---- layer 2 edge pass: single v4 red per edge ----
__global__ void k_edge2(const void* __restrict__ ei) {
    int e = blockIdx.x * blockDim.x + threadIdx.x;
    if (e >= NE) return;
    int is64 = g_is64;
    int src, dst;
    load_edge(ei, e, is64, src, dst);

    float4 s = g_src2[src];
    float v = s.z + g_ad2[dst];
    v = v > 0.f ? v : 0.2f * v;
    float w = __expf(v);
    asm volatile("red.global.add.v4.f32 [%0], {%1,%2,%3,%4};" ::"l"(g_acc2 + dst),
                 "f"(w * s.x), "f"(w * s.y), "f"(w), "f"(0.f)
                 : "memory");
}

// ---- finalize layer 2 + log_softmax ----
__global__ void k_fin2(float* __restrict__ out, const float* __restrict__ b2) {
    int n = blockIdx.x * blockDim.x + threadIdx.x;
    if (n >= NN) return;
    float4 acc = g_acc2[n];
    float4 s = g_src2[n];
    float v = s.z + g_ad2[n];
    v = v > 0.f ? v : 0.2f * v;
    float w = __expf(v);
    float inv = 1.f / (acc.z + w);
    float o0 = (acc.x + w * s.x) * inv + b2[0];
    float o1 = (acc.y + w * s.y) * inv + b2[1];
    float m = fmaxf(o0, o1);
    float lse = m + log1pf(__expf(fminf(o0, o1) - m));
    out[n * 2] = o0 - lse;
    out[n * 2 + 1] = o1 - lse;
}

extern "C" void kernel_launch(void* const* d_in, const int* in_sizes, int n_in,
                              void* d_out, int out_size) {
    const float* x   = (const float*)d_in[0];
    const void*  ei  = d_in[1];
    const float* W1  = (const float*)d_in[2];
    const float* as1 = (const float*)d_in[3];
    const float* ad1 = (const float*)d_in[4];
    const float* b1  = (const float*)d_in[5];
    const float* W2  = (const float*)d_in[6];
    const float* as2 = (const float*)d_in[7];
    const float* ad2 = (const float*)d_in[8];
    const float* b2  = (const float*)d_in[9];
    float* out = (float*)d_out;

    k_detect<<<1, 1>>>((const unsigned*)ei);
    k_prep1<<<(NN + 255) / 256, 256>>>(x, W1, as1, ad1);
    k_edge1<<<(NE + 255) / 256, 256>>>(ei);
    k_fin1<<<(NN + 31) / 32, 256>>>(W1, b1, W2, as2, ad2);
    k_edge2<<<(NE + 255) / 256, 256>>>(ei);
    k_fin2<<<(NN + 255) / 256, 256>>>(out, b2);
}

// round 3
// speedup vs baseline: 1.8102x; 1.3821x over previous
#include <cuda_runtime.h>

#define NN 100000
#define NE 1600000

// ---- device scratch ----
__device__ float g_sx  [NN * 8];   // {x0..x3} {x4,pad,pad,pad}
__device__ float g_as1 [NN * 8];   // per-head alpha_src
__device__ float g_ad1 [NN * 8];   // per-head alpha_dst
// acc1 layout per node (48 floats, stride 48):
//  [h*4 .. h*4+3]  = {Σw_h x0, Σw_h x1, Σw_h x2, Σw_h x3}   h=0..7   (offs 0..31)
//  [32+p*4 .. +3]  = {Σw_2p x4, Σw_2p, Σw_2p+1 x4, Σw_2p+1}  p=0..3  (offs 32..47)
__device__ float g_acc1[NN * 48];
__device__ float4 g_src2[NN];      // {h2_0, h2_1, alpha_src2, 0}
__device__ float  g_ad2 [NN];
__device__ float4 g_acc2[NN];      // {Σw h0, Σw h1, Σw, 0}
__device__ int    g_is64;

__device__ __forceinline__ void load_edge(const void* ei, int e, int is64,
                                          int& src, int& dst) {
    if (is64) {
        const long long* p = (const long long*)ei;
        src = (int)__ldg(p + e);
        dst = (int)__ldg(p + NE + e);
    } else {
        const int* p = (const int*)ei;
        src = __ldg(p + e);
        dst = __ldg(p + NE + e);
    }
}

// ---- layer 1 node prep + dtype detect + zero accumulators ----
__global__ void k_prep1(const float* __restrict__ x, const float* __restrict__ W1,
                        const float* __restrict__ aw, const float* __restrict__ bw,
                        const unsigned* __restrict__ ei) {
    __shared__ float sW[320], sA[64], sB[64];
    int t = threadIdx.x;
    if (blockIdx.x == 0 && t == 0)
        g_is64 = ((ei[1] | ei[3] | ei[5] | ei[7]) == 0u) ? 1 : 0;
    for (int i = t; i < 320; i += blockDim.x) sW[i] = W1[i];
    for (int i = t; i < 64; i += blockDim.x) { sA[i] = aw[i]; sB[i] = bw[i]; }
    __syncthreads();
    int n = blockIdx.x * blockDim.x + t;
    if (n >= NN) return;

    float xv[5];
#pragma unroll
    for (int k = 0; k < 5; k++) xv[k] = x[n * 5 + k];

    float4* sx = (float4*)(g_sx + n * 8);
    sx[0] = make_float4(xv[0], xv[1], xv[2], xv[3]);
    sx[1] = make_float4(xv[4], 0.f, 0.f, 0.f);

    float as[8], ad[8];
#pragma unroll
    for (int hh = 0; hh < 8; hh++) {
        float sa = 0.f, sb = 0.f;
#pragma unroll
        for (int c = 0; c < 8; c++) {
            int j = hh * 8 + c;
            float h = xv[0] * sW[j];
            h = fmaf(xv[1], sW[64 + j], h);
            h = fmaf(xv[2], sW[128 + j], h);
            h = fmaf(xv[3], sW[192 + j], h);
            h = fmaf(xv[4], sW[256 + j], h);
            sa = fmaf(h, sA[j], sa);
            sb = fmaf(h, sB[j], sb);
        }
        as[hh] = sa;
        ad[hh] = sb;
    }
    float4* ap = (float4*)(g_as1 + n * 8);
    ap[0] = make_float4(as[0], as[1], as[2], as[3]);
    ap[1] = make_float4(as[4], as[5], as[6], as[7]);
    float4* dp = (float4*)(g_ad1 + n * 8);
    dp[0] = make_float4(ad[0], ad[1], ad[2], ad[3]);
    dp[1] = make_float4(ad[4], ad[5], ad[6], ad[7]);

    float4 z = make_float4(0.f, 0.f, 0.f, 0.f);
    float4* cp = (float4*)(g_acc1 + (size_t)n * 48);
#pragma unroll
    for (int q = 0; q < 12; q++) cp[q] = z;
}

// ---- layer 1 edge pass: 4 threads/edge, 2 heads each, 3 red.v4 per thread ----
__global__ void k_edge1(const void* __restrict__ ei) {
    long long tid = (long long)blockIdx.x * blockDim.x + threadIdx.x;
    int e = (int)(tid >> 2);
    int k = (int)(tid & 3);
    if (e >= NE) return;
    int is64 = g_is64;
    int src, dst;
    load_edge(ei, e, is64, src, dst);

    float4 x03 = *(const float4*)(g_sx + src * 8);    // broadcast in warp
    float  x4  = g_sx[src * 8 + 4];
    float2 a = *(const float2*)(g_as1 + src * 8 + 2 * k);
    float2 d = *(const float2*)(g_ad1 + dst * 8 + 2 * k);

    float v0 = a.x + d.x; v0 = v0 > 0.f ? v0 : 0.2f * v0;
    float v1 = a.y + d.y; v1 = v1 > 0.f ? v1 : 0.2f * v1;
    float w0 = __expf(v0);
    float w1 = __expf(v1);

    float* base = g_acc1 + (size_t)dst * 48;
    asm volatile("red.global.add.v4.f32 [%0], {%1,%2,%3,%4};" ::"l"(
                     base + 8 * k),
                 "f"(w0 * x03.x), "f"(w0 * x03.y), "f"(w0 * x03.z), "f"(w0 * x03.w)
                 : "memory");
    asm volatile("red.global.add.v4.f32 [%0], {%1,%2,%3,%4};" ::"l"(
                     base + 8 * k + 4),
                 "f"(w1 * x03.x), "f"(w1 * x03.y), "f"(w1 * x03.z), "f"(w1 * x03.w)
                 : "memory");
    asm volatile("red.global.add.v4.f32 [%0], {%1,%2,%3,%4};" ::"l"(
                     base + 32 + 4 * k),
                 "f"(w0 * x4), "f"(w0), "f"(w1 * x4), "f"(w1)
                 : "memory");
}

// ---- finalize layer 1 + elu + bias + layer-2 projection, 8 threads/node ----
__global__ void k_fin1(const float* __restrict__ W1, const float* __restrict__ b1,
                       const float* __restrict__ W2, const float* __restrict__ a2,
                       const float* __restrict__ d2) {
    __shared__ float sW1[320], sb1[64], sW2[128], sa2[2], sd2[2];
    int t = threadIdx.x;
    for (int i = t; i < 320; i += blockDim.x) sW1[i] = W1[i];
    for (int i = t; i < 128; i += blockDim.x) sW2[i] = W2[i];
    for (int i = t; i < 64; i += blockDim.x) sb1[i] = b1[i];
    if (t < 2) { sa2[t] = a2[t]; sd2[t] = d2[t]; }
    __syncthreads();

    int n = blockIdx.x * 32 + (t >> 3);
    int hh = t & 7;
    if (n >= NN) return;

    const float* base = g_acc1 + (size_t)n * 48;
    float4 A = *(const float4*)(base + 4 * hh);        // Σw·x0..x3
    float2 T = *(const float2*)(base + 32 + 2 * hh);   // {Σw·x4, Σw}

    float ws = g_as1[n * 8 + hh] + g_ad1[n * 8 + hh];
    ws = ws > 0.f ? ws : 0.2f * ws;
    ws = __expf(ws);

    float x0 = g_sx[n * 8 + 0], x1 = g_sx[n * 8 + 1], x2 = g_sx[n * 8 + 2];
    float x3 = g_sx[n * 8 + 3], x4 = g_sx[n * 8 + 4];

    float inv = 1.f / (T.y + ws);
    float xa0 = (A.x + ws * x0) * inv;
    float xa1 = (A.y + ws * x1) * inv;
    float xa2 = (A.z + ws * x2) * inv;
    float xa3 = (A.w + ws * x3) * inv;
    float xa4 = (T.x + ws * x4) * inv;

    float h20 = 0.f, h21 = 0.f;
#pragma unroll
    for (int j = 0; j < 8; j++) {
        int jj = hh * 8 + j;
        float o = xa0 * sW1[jj];
        o = fmaf(xa1, sW1[64 + jj], o);
        o = fmaf(xa2, sW1[128 + jj], o);
        o = fmaf(xa3, sW1[192 + jj], o);
        o = fmaf(xa4, sW1[256 + jj], o);
        o += sb1[jj];
        o = o > 0.f ? o : __expf(o) - 1.f;  // elu
        h20 = fmaf(o, sW2[jj * 2], h20);
        h21 = fmaf(o, sW2[jj * 2 + 1], h21);
    }
#pragma unroll
    for (int m = 1; m < 8; m <<= 1) {
        h20 += __shfl_xor_sync(0xffffffffu, h20, m);
        h21 += __shfl_xor_sync(0xffffffffu, h21, m);
    }
    if (hh == 0) {
        float as2 = h20 * sa2[0] + h21 * sa2[1];
        float ad2 = h20 * sd2[0] + h21 * sd2[1];
        g_src2[n] = make_float4(h20, h21, as2, 0.f);
        g_ad2[n] = ad2;
        g_acc2[n] = make_float4(0.f, 0.f, 0.f, 0.f);
    }
}

// ---- layer 2 edge pass: single v4 red per edge ----
__global__ void k_edge2(const void* __restrict__ ei) {
    int e = blockIdx.x * blockDim.x + threadIdx.x;
    if (e >= NE) return;
    int is64 = g_is64;
    int src, dst;
    load_edge(ei, e, is64, src, dst);

    float4 s = g_src2[src];
    float v = s.z + g_ad2[dst];
    v = v > 0.f ? v : 0.2f * v;
    float w = __expf(v);
    asm volatile("red.global.add.v4.f32 [%0], {%1,%2,%3,%4};" ::"l"(g_acc2 + dst),
                 "f"(w * s.x), "f"(w * s.y), "f"(w), "f"(0.f)
                 : "memory");
}

// ---- finalize layer 2 + log_softmax ----
__global__ void k_fin2(float* __restrict__ out, const float* __restrict__ b2) {
    int n = blockIdx.x * blockDim.x + threadIdx.x;
    if (n >= NN) return;
    float4 acc = g_acc2[n];
    float4 s = g_src2[n];
    float v = s.z + g_ad2[n];
    v = v > 0.f ? v : 0.2f * v;
    float w = __expf(v);
    float inv = 1.f / (acc.z + w);
    float o0 = (acc.x + w * s.x) * inv + b2[0];
    float o1 = (acc.y + w * s.y) * inv + b2[1];
    float m = fmaxf(o0, o1);
    float lse = m + log1pf(__expf(fminf(o0, o1) - m));
    out[n * 2] = o0 - lse;
    out[n * 2 + 1] = o1 - lse;
}

extern "C" void kernel_launch(void* const* d_in, const int* in_sizes, int n_in,
                              void* d_out, int out_size) {
    const float* x   = (const float*)d_in[0];
    const void*  ei  = d_in[1];
    const float* W1  = (const float*)d_in[2];
    const float* as1 = (const float*)d_in[3];
    const float* ad1 = (const float*)d_in[4];
    const float* b1  = (const float*)d_in[5];
    const float* W2  = (const float*)d_in[6];
    const float* as2 = (const float*)d_in[7];
    const float* ad2 = (const float*)d_in[8];
    const float* b2  = (const float*)d_in[9];
    float* out = (float*)d_out;

    k_prep1<<<(NN + 255) / 256, 256>>>(x, W1, as1, ad1, (const unsigned*)ei);
    {
        long long total = (long long)NE * 4;
        k_edge1<<<(unsigned)((total + 255) / 256), 256>>>(ei);
    }
    k_fin1<<<(NN + 31) / 32, 256>>>(W1, b1, W2, as2, ad2);
    k_edge2<<<(NE + 255) / 256, 256>>>(ei);
    k_fin2<<<(NN + 255) / 256, 256>>>(out, b2);
}

// round 4
// speedup vs baseline: 2.4214x; 1.3376x over previous
#include <cuda_runtime.h>

#define NN 100000
#define NE 1600000
#define NB 391  // (NN+255)/256

// ---- device scratch ----
__device__ float  g_sx [NN * 8];   // {x0..x3} {x4,pad,pad,pad}
__device__ float  g_as1[NN * 8];   // per-head alpha_src
__device__ float  g_ad1[NN * 8];   // per-head alpha_dst
__device__ float4 g_src2[NN];      // {h2_0, h2_1, alpha_src2, 0}
__device__ float  g_ad2 [NN];
__device__ int    g_src32[NE];
__device__ int    g_dst32[NE];
__device__ int    g_deg[NN];
__device__ int    g_start[NN];
__device__ int    g_cursor[NN];
__device__ int    g_csr[NE];
__device__ int    g_bsum[NB];
__device__ int    g_boff[NB];
__device__ int    g_is64;

__device__ __forceinline__ void load_edge(const void* ei, int e, int is64,
                                          int& src, int& dst) {
    if (is64) {
        const long long* p = (const long long*)ei;
        src = (int)__ldg(p + e);
        dst = (int)__ldg(p + NE + e);
    } else {
        const int* p = (const int*)ei;
        src = __ldg(p + e);
        dst = __ldg(p + NE + e);
    }
}

// ---- node prep: sx, alpha_src/dst, zero degree, dtype detect ----
__global__ void k_prep1(const float* __restrict__ x, const float* __restrict__ W1,
                        const float* __restrict__ aw, const float* __restrict__ bw,
                        const unsigned* __restrict__ ei) {
    __shared__ float sW[320], sA[64], sB[64];
    int t = threadIdx.x;
    if (blockIdx.x == 0 && t == 0)
        g_is64 = ((ei[1] | ei[3] | ei[5] | ei[7]) == 0u) ? 1 : 0;
    for (int i = t; i < 320; i += blockDim.x) sW[i] = W1[i];
    for (int i = t; i < 64; i += blockDim.x) { sA[i] = aw[i]; sB[i] = bw[i]; }
    __syncthreads();
    int n = blockIdx.x * blockDim.x + t;
    if (n >= NN) return;

    g_deg[n] = 0;

    float xv[5];
#pragma unroll
    for (int k = 0; k < 5; k++) xv[k] = x[n * 5 + k];

    float4* sx = (float4*)(g_sx + n * 8);
    sx[0] = make_float4(xv[0], xv[1], xv[2], xv[3]);
    sx[1] = make_float4(xv[4], 0.f, 0.f, 0.f);

    float as[8], ad[8];
#pragma unroll
    for (int hh = 0; hh < 8; hh++) {
        float sa = 0.f, sb = 0.f;
#pragma unroll
        for (int c = 0; c < 8; c++) {
            int j = hh * 8 + c;
            float h = xv[0] * sW[j];
            h = fmaf(xv[1], sW[64 + j], h);
            h = fmaf(xv[2], sW[128 + j], h);
            h = fmaf(xv[3], sW[192 + j], h);
            h = fmaf(xv[4], sW[256 + j], h);
            sa = fmaf(h, sA[j], sa);
            sb = fmaf(h, sB[j], sb);
        }
        as[hh] = sa;
        ad[hh] = sb;
    }
    float4* ap = (float4*)(g_as1 + n * 8);
    ap[0] = make_float4(as[0], as[1], as[2], as[3]);
    ap[1] = make_float4(as[4], as[5], as[6], as[7]);
    float4* dp = (float4*)(g_ad1 + n * 8);
    dp[0] = make_float4(ad[0], ad[1], ad[2], ad[3]);
    dp[1] = make_float4(ad[4], ad[5], ad[6], ad[7]);
}

// ---- histogram of in-degrees + int32 edge copy ----
__global__ void k_hist(const void* __restrict__ ei) {
    int e = blockIdx.x * blockDim.x + threadIdx.x;
    if (e >= NE) return;
    int is64 = g_is64;
    int src, dst;
    load_edge(ei, e, is64, src, dst);
    g_src32[e] = src;
    g_dst32[e] = dst;
    atomicAdd(&g_deg[dst], 1);
}

// ---- scan phase 1: per-block degree sums ----
__global__ void k_scan1() {
    __shared__ int sh[256];
    int t = threadIdx.x;
    int n = blockIdx.x * 256 + t;
    sh[t] = n < NN ? g_deg[n] : 0;
    __syncthreads();
#pragma unroll
    for (int off = 128; off; off >>= 1) {
        if (t < off) sh[t] += sh[t + off];
        __syncthreads();
    }
    if (t == 0) g_bsum[blockIdx.x] = sh[0];
}

// ---- scan phase 2: exclusive scan of 391 block sums (1 block) ----
__global__ void k_scan2() {
    __shared__ int sh[512];
    int t = threadIdx.x;
    int v = t < NB ? g_bsum[t] : 0;
    sh[t] = v;
    __syncthreads();
#pragma unroll
    for (int off = 1; off < 512; off <<= 1) {
        int tmp = (t >= off) ? sh[t - off] : 0;
        __syncthreads();
        sh[t] += tmp;
        __syncthreads();
    }
    if (t < NB) g_boff[t] = sh[t] - v;
}

// ---- scan phase 3: per-block exclusive scan + offsets -> start/cursor ----
__global__ void k_scan3() {
    __shared__ int sh[256];
    int t = threadIdx.x;
    int n = blockIdx.x * 256 + t;
    int v = n < NN ? g_deg[n] : 0;
    sh[t] = v;
    __syncthreads();
#pragma unroll
    for (int off = 1; off < 256; off <<= 1) {
        int tmp = (t >= off) ? sh[t - off] : 0;
        __syncthreads();
        sh[t] += tmp;
        __syncthreads();
    }
    if (n < NN) {
        int s = g_boff[blockIdx.x] + sh[t] - v;
        g_start[n] = s;
        g_cursor[n] = s;
    }
}

// ---- scatter src ids into dst-CSR ----
__global__ void k_scatter() {
    int e = blockIdx.x * blockDim.x + threadIdx.x;
    if (e >= NE) return;
    int dst = g_dst32[e];
    int pos = atomicAdd(&g_cursor[dst], 1);
    g_csr[pos] = g_src32[e];
}

// ---- layer 1 aggregate + finalize + layer-2 projection (8 lanes/node) ----
__global__ void k_agg1(const float* __restrict__ W1, const float* __restrict__ b1,
                       const float* __restrict__ W2, const float* __restrict__ a2,
                       const float* __restrict__ d2) {
    __shared__ float sW1[320], sb1[64], sW2[128], sa2[2], sd2[2];
    int t = threadIdx.x;
    for (int i = t; i < 320; i += blockDim.x) sW1[i] = W1[i];
    for (int i = t; i < 128; i += blockDim.x) sW2[i] = W2[i];
    for (int i = t; i < 64; i += blockDim.x) sb1[i] = b1[i];
    if (t < 2) { sa2[t] = a2[t]; sd2[t] = d2[t]; }
    __syncthreads();

    int n = blockIdx.x * 32 + (t >> 3);  // 3125*32 == NN exactly, no tail
    int h = t & 7;

    int st = g_start[n];
    int dg = g_deg[n];
    float adh = g_ad1[n * 8 + h];

    float c0 = 0.f, c1 = 0.f, c2 = 0.f, c3 = 0.f, c4 = 0.f, dn = 0.f;
    for (int i = 0; i < dg; i++) {
        int src = __ldg(&g_csr[st + i]);
        float4 x03 = *(const float4*)(g_sx + src * 8);
        float x4 = g_sx[src * 8 + 4];
        float v = g_as1[src * 8 + h] + adh;
        v = v > 0.f ? v : 0.2f * v;
        float w = __expf(v);
        c0 = fmaf(w, x03.x, c0);
        c1 = fmaf(w, x03.y, c1);
        c2 = fmaf(w, x03.z, c2);
        c3 = fmaf(w, x03.w, c3);
        c4 = fmaf(w, x4, c4);
        dn += w;
    }
    // self loop
    {
        float4 x03 = *(const float4*)(g_sx + n * 8);
        float x4 = g_sx[n * 8 + 4];
        float v = g_as1[n * 8 + h] + adh;
        v = v > 0.f ? v : 0.2f * v;
        float w = __expf(v);
        c0 = fmaf(w, x03.x, c0);
        c1 = fmaf(w, x03.y, c1);
        c2 = fmaf(w, x03.z, c2);
        c3 = fmaf(w, x03.w, c3);
        c4 = fmaf(w, x4, c4);
        dn += w;
    }
    float inv = 1.f / dn;
    float xa0 = c0 * inv, xa1 = c1 * inv, xa2 = c2 * inv, xa3 = c3 * inv,
          xa4 = c4 * inv;

    float h20 = 0.f, h21 = 0.f;
#pragma unroll
    for (int j = 0; j < 8; j++) {
        int jj = h * 8 + j;
        float o = xa0 * sW1[jj];
        o = fmaf(xa1, sW1[64 + jj], o);
        o = fmaf(xa2, sW1[128 + jj], o);
        o = fmaf(xa3, sW1[192 + jj], o);
        o = fmaf(xa4, sW1[256 + jj], o);
        o += sb1[jj];
        o = o > 0.f ? o : __expf(o) - 1.f;  // elu
        h20 = fmaf(o, sW2[jj * 2], h20);
        h21 = fmaf(o, sW2[jj * 2 + 1], h21);
    }
#pragma unroll
    for (int m = 1; m < 8; m <<= 1) {
        h20 += __shfl_xor_sync(0xffffffffu, h20, m);
        h21 += __shfl_xor_sync(0xffffffffu, h21, m);
    }
    if (h == 0) {
        float as2v = h20 * sa2[0] + h21 * sa2[1];
        float ad2v = h20 * sd2[0] + h21 * sd2[1];
        g_src2[n] = make_float4(h20, h21, as2v, 0.f);
        g_ad2[n] = ad2v;
    }
}

// ---- layer 2 aggregate + finalize + log_softmax (1 thread/node) ----
__global__ void k_agg2(float* __restrict__ out, const float* __restrict__ b2) {
    int n = blockIdx.x * blockDim.x + threadIdx.x;
    if (n >= NN) return;
    int st = g_start[n];
    int dg = g_deg[n];
    float adn = g_ad2[n];

    float a0 = 0.f, a1 = 0.f, dn = 0.f;
#pragma unroll 4
    for (int i = 0; i < dg; i++) {
        int src = __ldg(&g_csr[st + i]);
        float4 s = g_src2[src];
        float v = s.z + adn;
        v = v > 0.f ? v : 0.2f * v;
        float w = __expf(v);
        a0 = fmaf(w, s.x, a0);
        a1 = fmaf(w, s.y, a1);
        dn += w;
    }
    // self loop
    float4 ss = g_src2[n];
    float v = ss.z + adn;
    v = v > 0.f ? v : 0.2f * v;
    float w = __expf(v);
    a0 = fmaf(w, ss.x, a0);
    a1 = fmaf(w, ss.y, a1);
    dn += w;

    float inv = 1.f / dn;
    float o0 = a0 * inv + __ldg(b2);
    float o1 = a1 * inv + __ldg(b2 + 1);
    float m = fmaxf(o0, o1);
    float lse = m + log1pf(__expf(fminf(o0, o1) - m));
    out[n * 2] = o0 - lse;
    out[n * 2 + 1] = o1 - lse;
}

extern "C" void kernel_launch(void* const* d_in, const int* in_sizes, int n_in,
                              void* d_out, int out_size) {
    const float* x   = (const float*)d_in[0];
    const void*  ei  = d_in[1];
    const float* W1  = (const float*)d_in[2];
    const float* as1 = (const float*)d_in[3];
    const float* ad1 = (const float*)d_in[4];
    const float* b1  = (const float*)d_in[5];
    const float* W2  = (const float*)d_in[6];
    const float* as2 = (const float*)d_in[7];
    const float* ad2 = (const float*)d_in[8];
    const float* b2  = (const float*)d_in[9];
    float* out = (float*)d_out;

    k_prep1<<<NB, 256>>>(x, W1, as1, ad1, (const unsigned*)ei);
    k_hist<<<(NE + 255) / 256, 256>>>(ei);
    k_scan1<<<NB, 256>>>();
    k_scan2<<<1, 512>>>();
    k_scan3<<<NB, 256>>>();
    k_scatter<<<(NE + 255) / 256, 256>>>();
    k_agg1<<<NN / 32, 256>>>(W1, b1, W2, as2, ad2);
    k_agg2<<<NB, 256>>>(out, b2);
}